// round 17
// baseline (speedup 1.0000x reference)
#include <cuda_runtime.h>
#include <cuda_bf16.h>
#include <cstdint>

// NT-Xent loss, B=4096, C=128 -> 8192 rows; sim = N N^T never materialized.
// R16: R12 design (A-tile-resident d-loop, 3 tile pairs per CTA, double-
// buffered B via cp.async) with the tile-load bug fixed: cpTile now copies
// all 2048 16B chunks per tile (R12 loaded only K columns 0..63 -> NaN).

#define NROWS 8192
#define HALFN 4096
#define CDIM  128
// exp(2*x) = 2^(x * 2*log2(e))
#define EXP_SCALE 2.8853900817779268f

// Scratch (device globals; no allocations allowed anywhere).
__device__ __align__(16) __nv_bfloat16 g_norm[NROWS * CDIM];  // row-major bf16
__device__ float g_part[64 * NROWS];   // per-tile-slot partial exp row sums
__device__ float g_pos[NROWS];         // positive-pair logit p_i
__device__ float g_bsum[64];           // per-block loss partials
__device__ unsigned g_ctr;             // last-block election counter

// Smem tile geometry: 128 rows x 128 bf16, row stride 136 bf16 (272 B) so
// ldmatrix 8-row phases hit distinct 16B bank groups (272 % 128 = 16).
#define ROWB   272
#define ATILE  (128 * ROWB)              // 34816 B
#define SMEM_BYTES (3 * ATILE + 3072)    // A + 2xB + reduction buffers

__device__ __forceinline__ uint32_t smem_u32(const void* p) {
    uint32_t a;
    asm("{ .reg .u64 t; cvta.to.shared.u64 t, %1; cvt.u32.u64 %0, t; }"
        : "=r"(a) : "l"(p));
    return a;
}

#define LDSM4(r, addr)                                                   \
    asm volatile("ldmatrix.sync.aligned.m8n8.x4.shared.b16 "             \
                 "{%0,%1,%2,%3}, [%4];"                                  \
                 : "=r"((r)[0]), "=r"((r)[1]), "=r"((r)[2]), "=r"((r)[3])\
                 : "r"(addr))

#define MMA16816(c, a, b0, b1)                                           \
    asm volatile("mma.sync.aligned.m16n8k16.row.col.f32.bf16.bf16.f32 "  \
                 "{%0,%1,%2,%3}, {%4,%5,%6,%7}, {%8,%9}, {%0,%1,%2,%3};" \
                 : "+f"((c)[0]), "+f"((c)[1]), "+f"((c)[2]), "+f"((c)[3])\
                 : "r"((a)[0]), "r"((a)[1]), "r"((a)[2]), "r"((a)[3]),   \
                   "r"(b0), "r"(b1))

#define CP_ASYNC16(saddr, gptr)                                          \
    asm volatile("cp.async.cg.shared.global [%0], [%1], 16;"             \
                 :: "r"(saddr), "l"(gptr))
#define CP_COMMIT() asm volatile("cp.async.commit_group;" ::: "memory")
#define CP_WAIT(n)  asm volatile("cp.async.wait_group %0;" :: "n"(n) : "memory")

// ---------------------------------------------------------------------------
// Kernel 1: four rows per warp (8 lanes each), 4 independent float4 loads per
// thread (MLP=4), 8-lane shuffle reduce, emit row-major bf16.
// ---------------------------------------------------------------------------
__global__ void norm_kernel(const float* __restrict__ zi,
                            const float* __restrict__ zj) {
    const int w = (blockIdx.x * blockDim.x + threadIdx.x) >> 5;
    const int lane = threadIdx.x & 31;
    const int r = 4 * w + (lane >> 3);
    const int l8 = lane & 7;
    if (r >= NROWS) return;
    const float* src = (r < HALFN) ? (zi + (size_t)r * CDIM)
                                   : (zj + (size_t)(r - HALFN) * CDIM);
    float4 v[4];
#pragma unroll
    for (int j = 0; j < 4; j++)
        v[j] = reinterpret_cast<const float4*>(src)[l8 + 8 * j];
    float ss = 0.0f;
#pragma unroll
    for (int j = 0; j < 4; j++)
        ss += v[j].x * v[j].x + v[j].y * v[j].y + v[j].z * v[j].z + v[j].w * v[j].w;
#pragma unroll
    for (int o = 4; o; o >>= 1) ss += __shfl_xor_sync(0xFFFFFFFFu, ss, o);
    float rinv = rsqrtf(ss);
    uint2* dst = reinterpret_cast<uint2*>(g_norm + (size_t)r * CDIM);
#pragma unroll
    for (int j = 0; j < 4; j++) {
        __nv_bfloat162 a = __floats2bfloat162_rn(v[j].x * rinv, v[j].y * rinv);
        __nv_bfloat162 b = __floats2bfloat162_rn(v[j].z * rinv, v[j].w * rinv);
        uint2 pk;
        pk.x = *reinterpret_cast<uint32_t*>(&a);
        pk.y = *reinterpret_cast<uint32_t*>(&b);
        dst[l8 + 8 * j] = pk;
    }
}

// ---------------------------------------------------------------------------
// Epilogue: exp + BOTH row sums and column sums over the 4x4 acc grid.
// CHECK handles diagonal zeroing (d==0) and positive-pair capture (d==32).
// redR: [128][4] per-(row, wn) partials.  redC: [128][2] per-(col, wm).
// ---------------------------------------------------------------------------
template <bool CHECK>
__device__ __forceinline__ void epilogue(float acc[4][4][4], float* redR,
                                         float* redC, int rowbase, int colbase,
                                         int wm, int wn, int lane) {
    float csum[4][2];
#pragma unroll
    for (int nt = 0; nt < 4; nt++) csum[nt][0] = csum[nt][1] = 0.0f;

#pragma unroll
    for (int mt = 0; mt < 4; mt++) {
        const int r0 = wm * 64 + mt * 16 + (lane >> 2);   // local row
        const int gr0 = rowbase + r0;
        const int gr1 = gr0 + 8;
        const int p0 = (gr0 + HALFN) & (NROWS - 1);
        const int p1 = (gr1 + HALFN) & (NROWS - 1);
        float rs0 = 0.0f, rs1 = 0.0f;
#pragma unroll
        for (int nt = 0; nt < 4; nt++) {
            const int gc = colbase + wn * 32 + nt * 8 + (lane & 3) * 2;
            float v0 = acc[mt][nt][0], v1 = acc[mt][nt][1];
            float v2 = acc[mt][nt][2], v3 = acc[mt][nt][3];
            float e0 = exp2f(v0 * EXP_SCALE);
            float e1 = exp2f(v1 * EXP_SCALE);
            float e2 = exp2f(v2 * EXP_SCALE);
            float e3 = exp2f(v3 * EXP_SCALE);
            if (CHECK) {
                if (gc + 0 == gr0) e0 = 0.0f;          // diagonal (d==0)
                if (gc + 1 == gr0) e1 = 0.0f;
                if (gc + 0 == gr1) e2 = 0.0f;
                if (gc + 1 == gr1) e3 = 0.0f;
                if (gc + 0 == p0) { g_pos[gr0] = 2.0f * v0; g_pos[gc + 0] = 2.0f * v0; }
                if (gc + 1 == p0) { g_pos[gr0] = 2.0f * v1; g_pos[gc + 1] = 2.0f * v1; }
                if (gc + 0 == p1) { g_pos[gr1] = 2.0f * v2; g_pos[gc + 0] = 2.0f * v2; }
                if (gc + 1 == p1) { g_pos[gr1] = 2.0f * v3; g_pos[gc + 1] = 2.0f * v3; }
            }
            rs0 += e0 + e1;
            rs1 += e2 + e3;
            csum[nt][0] += e0 + e2;
            csum[nt][1] += e1 + e3;
        }
        // reduce rows across the 4 lanes sharing each row
        rs0 += __shfl_xor_sync(0xFFFFFFFFu, rs0, 1);
        rs0 += __shfl_xor_sync(0xFFFFFFFFu, rs0, 2);
        rs1 += __shfl_xor_sync(0xFFFFFFFFu, rs1, 1);
        rs1 += __shfl_xor_sync(0xFFFFFFFFu, rs1, 2);
        if ((lane & 3) == 0) {
            redR[r0 * 4 + wn] = rs0;
            redR[(r0 + 8) * 4 + wn] = rs1;
        }
    }

    // reduce columns across the 8 lanes sharing each column (same lane&3)
#pragma unroll
    for (int nt = 0; nt < 4; nt++)
#pragma unroll
        for (int c = 0; c < 2; c++) {
            float s = csum[nt][c];
            s += __shfl_xor_sync(0xFFFFFFFFu, s, 4);
            s += __shfl_xor_sync(0xFFFFFFFFu, s, 8);
            s += __shfl_xor_sync(0xFFFFFFFFu, s, 16);
            csum[nt][c] = s;
        }
    if (lane < 4) {
#pragma unroll
        for (int nt = 0; nt < 4; nt++)
#pragma unroll
            for (int c = 0; c < 2; c++)
                redC[(wn * 32 + nt * 8 + lane * 2 + c) * 2 + wm] = csum[nt][c];
    }
}

// ---------------------------------------------------------------------------
// Kernel 2: grid (64 bx, 11 s). CTA (bx, s) keeps A(bx) resident and loops
// over d = 3s+i, i in [0, cnt): by = (bx+d)&63. d ranges over 0..32 exactly
// once across s; d==32 only applies to bx<32 (cnt accounts for this).
// B tiles double-buffered; B[i+1] prefetch overlaps tile-i MMA + epilogue.
// Writes rowsums -> g_part[by][bx-rows]; colsums -> g_part[bx][by-rows]
// (skipped for d==0). Unique writer per slot, no atomics.
// ---------------------------------------------------------------------------
__global__ void __launch_bounds__(256, 2)
simexp_mma() {
    const int bx = blockIdx.x;
    const int s = blockIdx.y;
    const int cnt = (s == 10) ? ((bx < 32) ? 3 : 2) : 3;

    extern __shared__ char smem[];
    char* sA = smem;
    const uint32_t sAu = smem_u32(sA);
    const uint32_t sBu0 = sAu + ATILE;
    const uint32_t sBu1 = sAu + 2 * ATILE;
    float* redR = reinterpret_cast<float*>(smem + 3 * ATILE);   // [128][4]
    float* redC = redR + 512;                                   // [128][2]

    const int tid = threadIdx.x;
    const int wid = tid >> 5;
    const int lane = tid & 31;
    const int wm = wid >> 2;
    const int wn = wid & 3;
    const int rowbase = bx * 128;

    const uint4* gsrc = reinterpret_cast<const uint4*>(g_norm);

    // cp.async helper: each tile = 2048 16B chunks (128 rows x 16 chunks).
    auto cpTile = [&](uint32_t sbase, int grow0) {
#pragma unroll
        for (int i = 0; i < 8; i++) {
            const int idx = tid + i * 256;        // 0..2047
            const int row = idx >> 4;             // 0..127
            const int ch = idx & 15;              // 0..15
            CP_ASYNC16(sbase + row * ROWB + ch * 16,
                       gsrc + (size_t)(grow0 + row) * 16 + ch);
        }
    };

    // Prologue: G0 = {A, B0}; G1 = {B1}.
    cpTile(sAu, rowbase);
    cpTile(sBu0, ((bx + 3 * s + 0) & 63) * 128);
    CP_COMMIT();
    if (cnt > 1) cpTile(sBu1, ((bx + 3 * s + 1) & 63) * 128);
    CP_COMMIT();

    // Fixed A ldmatrix base; B base toggles per iteration.
    const uint32_t aBase = sAu
        + (wm * 64 + (lane & 15)) * ROWB + (lane >> 4) * 16;
    const uint32_t bOff =
        (wn * 32 + (lane & 7) + ((lane >> 4) & 1) * 8) * ROWB
        + ((lane >> 3) & 1) * 16;

    for (int it = 0; it < cnt; it++) {
        const int d = 3 * s + it;
        const int by = (bx + d) & 63;
        const int colbase = by * 128;
        const uint32_t bBase = ((it & 1) ? sBu1 : sBu0) + bOff;

        CP_WAIT(1);            // tile-it's group has landed
        __syncthreads();

        float acc[4][4][4];
#pragma unroll
        for (int mt = 0; mt < 4; mt++)
#pragma unroll
            for (int nt = 0; nt < 4; nt++)
#pragma unroll
                for (int c = 0; c < 4; c++) acc[mt][nt][c] = 0.0f;

#pragma unroll
        for (int ks = 0; ks < 8; ks++) {
            uint32_t a[4][4];
#pragma unroll
            for (int mt = 0; mt < 4; mt++)
                LDSM4(a[mt], aBase + mt * 16 * ROWB + ks * 32);
            uint32_t b[2][4];
#pragma unroll
            for (int np = 0; np < 2; np++)
                LDSM4(b[np], bBase + np * 16 * ROWB + ks * 32);
#pragma unroll
            for (int mt = 0; mt < 4; mt++)
#pragma unroll
                for (int nt = 0; nt < 4; nt++)
                    MMA16816(acc[mt][nt], a[mt],
                             b[nt >> 1][(nt & 1) * 2],
                             b[nt >> 1][(nt & 1) * 2 + 1]);
        }

        __syncthreads();       // all warps done reading buf (it&1)
        if (it + 2 < cnt)      // prefetch B[it+2] into the freed buffer
            cpTile((it & 1) ? sBu1 : sBu0, ((bx + 3 * s + it + 2) & 63) * 128);
        CP_COMMIT();           // always commit to keep group counting uniform

        if (d == 0 || d == 32)
            epilogue<true>(acc, redR, redC, rowbase, colbase, wm, wn, lane);
        else
            epilogue<false>(acc, redR, redC, rowbase, colbase, wm, wn, lane);

        __syncthreads();
        if (tid < 128) {
            float rs = redR[tid * 4 + 0] + redR[tid * 4 + 1]
                     + redR[tid * 4 + 2] + redR[tid * 4 + 3];
            g_part[(size_t)by * NROWS + rowbase + tid] = rs;
            if (d != 0) {
                float cs = redC[tid * 2 + 0] + redC[tid * 2 + 1];
                g_part[(size_t)bx * NROWS + colbase + tid] = cs;
            }
        }
    }
}

// ---------------------------------------------------------------------------
// Kernel 3: per-row loss + fused final mean (deterministic last-block).
// loss_i = log(S_i + exp(p_i)) - p_i
// ---------------------------------------------------------------------------
__global__ void loss_kernel(float* __restrict__ out) {
    const int tid = threadIdx.x;
    const int i = blockIdx.x * 128 + tid;
    float S = 0.0f;
#pragma unroll
    for (int t = 0; t < 64; t++) S += g_part[(size_t)t * NROWS + i];
    const float p = g_pos[i];
    float li = logf(S + __expf(p)) - p;
    __shared__ float red[128];
    __shared__ bool last;
    red[tid] = li;
    __syncthreads();
    for (int s = 64; s > 0; s >>= 1) {
        if (tid < s) red[tid] += red[tid + s];
        __syncthreads();
    }
    if (tid == 0) {
        g_bsum[blockIdx.x] = red[0];
        __threadfence();
        last = (atomicAdd(&g_ctr, 1u) == 63u);
    }
    __syncthreads();
    if (last && tid < 32) {
        float s = g_bsum[tid] + g_bsum[tid + 32];
#pragma unroll
        for (int o = 16; o; o >>= 1) s += __shfl_xor_sync(0xFFFFFFFFu, s, o);
        if (tid == 0) {
            out[0] = s * (1.0f / (float)NROWS);
            g_ctr = 0;   // reset for the next (graph-replayed) call
        }
    }
}

// ---------------------------------------------------------------------------
extern "C" void kernel_launch(void* const* d_in, const int* in_sizes, int n_in,
                              void* d_out, int out_size) {
    const float* zi = (const float*)d_in[0];
    const float* zj = (const float*)d_in[1];
    float* out = (float*)d_out;

    norm_kernel<<<NROWS / 4 / 8, 256>>>(zi, zj);

    cudaFuncSetAttribute(simexp_mma,
                         cudaFuncAttributeMaxDynamicSharedMemorySize,
                         SMEM_BYTES);
    simexp_mma<<<dim3(64, 11), 256, SMEM_BYTES>>>();

    loss_kernel<<<64, 128>>>(out);
}